// round 4
// baseline (speedup 1.0000x reference)
#include <cuda_runtime.h>
#include <math.h>
#include <stdint.h>

#define D_EMB   1024
#define N_HEADS 16
#define DK      64
#define BATCH   2
#define SEQ     2048
#define MROWS   (BATCH*SEQ)   // 4096

// Scratch (allocation-free rule: __device__ globals)
__device__ float g_q[MROWS * D_EMB];
__device__ float g_k[MROWS * D_EMB];
__device__ float g_v[MROWS * D_EMB];
__device__ float g_attn[MROWS * D_EMB];

__device__ __forceinline__ float to_tf32(float x) {
    asm("cvt.rna.tf32.f32 %0, %0;" : "+f"(x));
    return x;
}

__device__ __forceinline__ uint32_t smem_u32(const void* p) {
    return (uint32_t)__cvta_generic_to_shared(p);
}

#define CP_ASYNC16(dst_u32, src_ptr) \
    asm volatile("cp.async.cg.shared.global [%0], [%1], 16;\n" \
                 :: "r"(dst_u32), "l"(src_ptr))
#define CP_COMMIT() asm volatile("cp.async.commit_group;\n")
#define CP_WAIT(n)  asm volatile("cp.async.wait_group %0;\n" :: "n"(n))

__device__ __forceinline__ void mma_tf32(float d[4],
                                         uint32_t a0, uint32_t a1, uint32_t a2, uint32_t a3,
                                         uint32_t b0, uint32_t b1)
{
    asm volatile(
        "mma.sync.aligned.m16n8k8.row.col.f32.tf32.tf32.f32 "
        "{%0,%1,%2,%3}, {%4,%5,%6,%7}, {%8,%9}, {%0,%1,%2,%3};\n"
        : "+f"(d[0]), "+f"(d[1]), "+f"(d[2]), "+f"(d[3])
        : "r"(a0), "r"(a1), "r"(a2), "r"(a3), "r"(b0), "r"(b1));
}

// ---------------------------------------------------------------------------
// tf32 GEMM (NT + bias): C[m,n] = sum_k A[m,k]*W[n,k] + bias[n]
// BM=BN=128, BK=32, 256 threads = 8 warps (2x4), warp tile 64x32.
// OutMode: 0 = plain fp32, 1 = tf32-rounded, 2 = tf32-rounded * 0.125 (Q)
// ---------------------------------------------------------------------------
#define GP 36

template<int OutMode>
__global__ __launch_bounds__(256, 2)
void gemm_tf32(const float* __restrict__ A,
               const float* __restrict__ W,
               const float* __restrict__ bias,
               float* __restrict__ C)
{
    __shared__ float As[128 * GP];
    __shared__ float Ws[128 * GP];
    const uint32_t* Asu = (const uint32_t*)As;
    const uint32_t* Wsu = (const uint32_t*)Ws;

    const int t    = threadIdx.x;
    const int lane = t & 31;
    const int w    = t >> 5;
    const int wm   = w >> 2;     // 0..1
    const int wn   = w & 3;      // 0..3
    const int m0   = blockIdx.y * 128;
    const int n0   = blockIdx.x * 128;

    const int lrow = t >> 3;     // 0..31
    const int kq   = t & 7;      // float4 index within the 32-wide k slab
    const float* Ag = A + (size_t)(m0 + lrow) * D_EMB + kq * 4;
    const float* Wg = W + (size_t)(n0 + lrow) * D_EMB + kq * 4;

    float acc[4][4][4];
#pragma unroll
    for (int i = 0; i < 4; ++i)
#pragma unroll
        for (int j = 0; j < 4; ++j)
#pragma unroll
            for (int q = 0; q < 4; ++q) acc[i][j][q] = 0.f;

    float4 ra[4], rw[4];

#pragma unroll
    for (int i = 0; i < 4; ++i) {
        ra[i] = *(const float4*)(Ag + (size_t)i * 32 * D_EMB);
        rw[i] = *(const float4*)(Wg + (size_t)i * 32 * D_EMB);
    }
#pragma unroll
    for (int i = 0; i < 4; ++i) {
        float4 va = ra[i], vw = rw[i];
        float* pa = &As[(lrow + 32 * i) * GP + kq * 4];
        pa[0] = to_tf32(va.x); pa[1] = to_tf32(va.y);
        pa[2] = to_tf32(va.z); pa[3] = to_tf32(va.w);
        float* pw = &Ws[(lrow + 32 * i) * GP + kq * 4];
        pw[0] = to_tf32(vw.x); pw[1] = to_tf32(vw.y);
        pw[2] = to_tf32(vw.z); pw[3] = to_tf32(vw.w);
    }
    __syncthreads();

    for (int kt = 0; kt < D_EMB / 32; ++kt) {
        if (kt < D_EMB / 32 - 1) {
            const float* a  = Ag + (kt + 1) * 32;
            const float* wp = Wg + (kt + 1) * 32;
#pragma unroll
            for (int i = 0; i < 4; ++i) {
                ra[i] = *(const float4*)(a + (size_t)i * 32 * D_EMB);
                rw[i] = *(const float4*)(wp + (size_t)i * 32 * D_EMB);
            }
        }

#pragma unroll
        for (int ks = 0; ks < 4; ++ks) {
            const int c = ks * 8 + (lane & 3);
            uint32_t af[4][4];
#pragma unroll
            for (int mt = 0; mt < 4; ++mt) {
                const int r = wm * 64 + mt * 16 + (lane >> 2);
                af[mt][0] = Asu[r * GP + c];
                af[mt][1] = Asu[(r + 8) * GP + c];
                af[mt][2] = Asu[r * GP + c + 4];
                af[mt][3] = Asu[(r + 8) * GP + c + 4];
            }
            uint32_t bf[4][2];
#pragma unroll
            for (int nt = 0; nt < 4; ++nt) {
                const int n = wn * 32 + nt * 8 + (lane >> 2);
                bf[nt][0] = Wsu[n * GP + c];
                bf[nt][1] = Wsu[n * GP + c + 4];
            }
#pragma unroll
            for (int mt = 0; mt < 4; ++mt)
#pragma unroll
                for (int nt = 0; nt < 4; ++nt)
                    mma_tf32(acc[mt][nt], af[mt][0], af[mt][1], af[mt][2], af[mt][3],
                             bf[nt][0], bf[nt][1]);
        }

        if (kt < D_EMB / 32 - 1) {
            __syncthreads();
#pragma unroll
            for (int i = 0; i < 4; ++i) {
                float4 va = ra[i], vw = rw[i];
                float* pa = &As[(lrow + 32 * i) * GP + kq * 4];
                pa[0] = to_tf32(va.x); pa[1] = to_tf32(va.y);
                pa[2] = to_tf32(va.z); pa[3] = to_tf32(va.w);
                float* pw = &Ws[(lrow + 32 * i) * GP + kq * 4];
                pw[0] = to_tf32(vw.x); pw[1] = to_tf32(vw.y);
                pw[2] = to_tf32(vw.z); pw[3] = to_tf32(vw.w);
            }
            __syncthreads();
        }
    }

#pragma unroll
    for (int mt = 0; mt < 4; ++mt) {
        const int r = m0 + wm * 64 + mt * 16 + (lane >> 2);
#pragma unroll
        for (int nt = 0; nt < 4; ++nt) {
            const int n = n0 + wn * 32 + nt * 8 + (lane & 3) * 2;
            const float b0 = __ldg(&bias[n]);
            const float b1 = __ldg(&bias[n + 1]);
            float v00 = acc[mt][nt][0] + b0, v01 = acc[mt][nt][1] + b1;
            float v10 = acc[mt][nt][2] + b0, v11 = acc[mt][nt][3] + b1;
            if (OutMode == 2) {
                v00 *= 0.125f; v01 *= 0.125f; v10 *= 0.125f; v11 *= 0.125f;
            }
            if (OutMode != 0) {
                v00 = to_tf32(v00); v01 = to_tf32(v01);
                v10 = to_tf32(v10); v11 = to_tf32(v11);
            }
            *(float2*)&C[(size_t)r * D_EMB + n]       = make_float2(v00, v01);
            *(float2*)&C[(size_t)(r + 8) * D_EMB + n] = make_float2(v10, v11);
        }
    }
}

// ---------------------------------------------------------------------------
// Flash attention, tf32 mma, P in registers, cp.async double-buffered K/V.
// Inputs g_q/g_k/g_v are already tf32-rounded (Q also pre-scaled by 1/8).
// Grid (S/128, H, B), 128 threads = 4 warps; each warp owns 32 query rows.
// SMEM: Qs[128][68], K/V ring: 2 x (Ks[64][68] + Vs[64][68]).
// ---------------------------------------------------------------------------
#define AP 68
#define ATTN_SMEM_BYTES ((128 * AP + 4 * 64 * AP) * 4)

__global__ __launch_bounds__(128)
void attn_tf32(float* __restrict__ out)
{
    extern __shared__ float sm[];
    float* Qs = sm;                        // [q][d] pitch AP, 128 rows
    float* Kbuf[2] = { Qs + 128 * AP,            Qs + 128 * AP + 2 * 64 * AP };
    float* Vbuf[2] = { Qs + 128 * AP + 64 * AP,  Qs + 128 * AP + 3 * 64 * AP };
    const uint32_t* Qsu = (const uint32_t*)Qs;

    const int t    = threadIdx.x;
    const int lane = t & 31;
    const int warp = t >> 5;
    const int r    = lane >> 2;            // 0..7
    const int cg   = lane & 3;             // 0..3
    const int q0   = blockIdx.x * 128;
    const int h    = blockIdx.y;
    const int b    = blockIdx.z;

    const float* qptr = g_q + (size_t)(b * SEQ) * D_EMB + h * DK;
    const float* kptr = g_k + (size_t)(b * SEQ) * D_EMB + h * DK;
    const float* vptr = g_v + (size_t)(b * SEQ) * D_EMB + h * DK;

    // Prologue group: Q tile + K/V tile 0.
#pragma unroll
    for (int it = 0; it < 16; ++it) {
        const int idx = t + it * 128;       // 0..2047
        const int row = idx >> 4, f4 = idx & 15;
        CP_ASYNC16(smem_u32(&Qs[row * AP + f4 * 4]),
                   &qptr[(size_t)(q0 + row) * D_EMB + f4 * 4]);
    }
#pragma unroll
    for (int it = 0; it < 8; ++it) {
        const int idx = t + it * 128;       // 0..1023
        const int row = idx >> 4, f4 = idx & 15;
        CP_ASYNC16(smem_u32(&Kbuf[0][row * AP + f4 * 4]),
                   &kptr[(size_t)row * D_EMB + f4 * 4]);
        CP_ASYNC16(smem_u32(&Vbuf[0][row * AP + f4 * 4]),
                   &vptr[(size_t)row * D_EMB + f4 * 4]);
    }
    CP_COMMIT();

    float m_[2][2], l_[2][2];
    float o[2][8][4];
#pragma unroll
    for (int mt = 0; mt < 2; ++mt) {
        m_[mt][0] = m_[mt][1] = -INFINITY;
        l_[mt][0] = l_[mt][1] = 0.f;
#pragma unroll
        for (int nt = 0; nt < 8; ++nt)
#pragma unroll
            for (int q = 0; q < 4; ++q) o[mt][nt][q] = 0.f;
    }

    for (int kt = 0; kt < SEQ / 64; ++kt) {
        // Prefetch next tile into the other buffer.
        if (kt + 1 < SEQ / 64) {
            const int nb = (kt + 1) & 1;
            const size_t nbase = (size_t)(kt + 1) * 64;
#pragma unroll
            for (int it = 0; it < 8; ++it) {
                const int idx = t + it * 128;
                const int row = idx >> 4, f4 = idx & 15;
                CP_ASYNC16(smem_u32(&Kbuf[nb][row * AP + f4 * 4]),
                           &kptr[(nbase + row) * D_EMB + f4 * 4]);
                CP_ASYNC16(smem_u32(&Vbuf[nb][row * AP + f4 * 4]),
                           &vptr[(nbase + row) * D_EMB + f4 * 4]);
            }
            CP_COMMIT();
            CP_WAIT(1);
        } else {
            CP_WAIT(0);
        }
        __syncthreads();

        const uint32_t* Ksu = (const uint32_t*)Kbuf[kt & 1];
        const uint32_t* Vsu = (const uint32_t*)Vbuf[kt & 1];

        // S = Q * K^T  (32 q rows per warp x 64 keys)
        float s[2][8][4];
#pragma unroll
        for (int mt = 0; mt < 2; ++mt)
#pragma unroll
            for (int nt = 0; nt < 8; ++nt)
#pragma unroll
                for (int q = 0; q < 4; ++q) s[mt][nt][q] = 0.f;

#pragma unroll
        for (int ks = 0; ks < 8; ++ks) {
            const int c = ks * 8 + cg;
#pragma unroll
            for (int mt = 0; mt < 2; ++mt) {
                const int qr = warp * 32 + mt * 16 + r;
                const uint32_t a0 = Qsu[qr * AP + c];
                const uint32_t a1 = Qsu[(qr + 8) * AP + c];
                const uint32_t a2 = Qsu[qr * AP + c + 4];
                const uint32_t a3 = Qsu[(qr + 8) * AP + c + 4];
#pragma unroll
                for (int nt = 0; nt < 8; ++nt) {
                    const int n = nt * 8 + r;
                    mma_tf32(s[mt][nt], a0, a1, a2, a3,
                             Ksu[n * AP + c], Ksu[n * AP + c + 4]);
                }
            }
        }

        // Online softmax (rows r / r+8 per 16-row tile; lane row-group = cg).
#pragma unroll
        for (int mt = 0; mt < 2; ++mt) {
#pragma unroll
            for (int hlf = 0; hlf < 2; ++hlf) {
                float mx = -INFINITY;
#pragma unroll
                for (int nt = 0; nt < 8; ++nt)
                    mx = fmaxf(mx, fmaxf(s[mt][nt][2 * hlf], s[mt][nt][2 * hlf + 1]));
                mx = fmaxf(mx, __shfl_xor_sync(0xffffffffu, mx, 1));
                mx = fmaxf(mx, __shfl_xor_sync(0xffffffffu, mx, 2));
                const float mnew  = fmaxf(m_[mt][hlf], mx);
                const float alpha = __expf(m_[mt][hlf] - mnew);
                m_[mt][hlf] = mnew;
                float rs = 0.f;
#pragma unroll
                for (int nt = 0; nt < 8; ++nt) {
                    float p0 = __expf(s[mt][nt][2 * hlf]     - mnew);
                    float p1 = __expf(s[mt][nt][2 * hlf + 1] - mnew);
                    rs += p0 + p1;
                    s[mt][nt][2 * hlf]     = to_tf32(p0);
                    s[mt][nt][2 * hlf + 1] = to_tf32(p1);
                }
                rs += __shfl_xor_sync(0xffffffffu, rs, 1);
                rs += __shfl_xor_sync(0xffffffffu, rs, 2);
                l_[mt][hlf] = l_[mt][hlf] * alpha + rs;
#pragma unroll
                for (int nt = 0; nt < 8; ++nt) {
                    o[mt][nt][2 * hlf]     *= alpha;
                    o[mt][nt][2 * hlf + 1] *= alpha;
                }
            }
        }

        // O += P * V, P straight from registers (C-frag -> A-frag via the
        // within-8 key permutation, undone by permuted V row reads).
#pragma unroll
        for (int ks = 0; ks < 8; ++ks) {
            const int v0row = ks * 8 + 2 * cg;
#pragma unroll
            for (int mt = 0; mt < 2; ++mt) {
                const uint32_t a0 = __float_as_uint(s[mt][ks][0]);
                const uint32_t a1 = __float_as_uint(s[mt][ks][2]);
                const uint32_t a2 = __float_as_uint(s[mt][ks][1]);
                const uint32_t a3 = __float_as_uint(s[mt][ks][3]);
#pragma unroll
                for (int nt = 0; nt < 8; ++nt) {
                    const int n = nt * 8 + r;
                    mma_tf32(o[mt][nt], a0, a1, a2, a3,
                             Vsu[v0row * AP + n], Vsu[(v0row + 1) * AP + n]);
                }
            }
        }
        __syncthreads();   // release buf[kt&1] for the kt+2 prefetch
    }

    // Normalize and write out[b, q, h*64 + d].
#pragma unroll
    for (int mt = 0; mt < 2; ++mt) {
        const float inv0 = 1.f / l_[mt][0];
        const float inv1 = 1.f / l_[mt][1];
        const size_t row0 = (size_t)(b * SEQ + q0 + warp * 32 + mt * 16 + r) * D_EMB + h * DK;
        const size_t row1 = row0 + 8 * D_EMB;
#pragma unroll
        for (int nt = 0; nt < 8; ++nt) {
            const int col = nt * 8 + cg * 2;
            *(float2*)&out[row0 + col] = make_float2(o[mt][nt][0] * inv0, o[mt][nt][1] * inv0);
            *(float2*)&out[row1 + col] = make_float2(o[mt][nt][2] * inv1, o[mt][nt][3] * inv1);
        }
    }
}

// ---------------------------------------------------------------------------
extern "C" void kernel_launch(void* const* d_in, const int* in_sizes, int n_in,
                              void* d_out, int out_size)
{
    const float* Q   = (const float*)d_in[0];
    const float* K   = (const float*)d_in[1];
    const float* V   = (const float*)d_in[2];
    const float* W_Q = (const float*)d_in[3];
    const float* b_Q = (const float*)d_in[4];
    const float* W_K = (const float*)d_in[5];
    const float* b_K = (const float*)d_in[6];
    const float* W_V = (const float*)d_in[7];
    const float* b_V = (const float*)d_in[8];
    const float* W_O = (const float*)d_in[9];
    const float* b_O = (const float*)d_in[10];
    float* out = (float*)d_out;

    float* gq; cudaGetSymbolAddress((void**)&gq, g_q);
    float* gk; cudaGetSymbolAddress((void**)&gk, g_k);
    float* gv; cudaGetSymbolAddress((void**)&gv, g_v);
    float* ga; cudaGetSymbolAddress((void**)&ga, g_attn);

    cudaFuncSetAttribute(attn_tf32,
                         cudaFuncAttributeMaxDynamicSharedMemorySize,
                         ATTN_SMEM_BYTES);

    dim3 gblk(256);
    dim3 ggrd(D_EMB / 128, MROWS / 128);   // (8, 32)

    gemm_tf32<2><<<ggrd, gblk>>>(Q, W_Q, b_Q, gq);   // tf32 + 1/8 scale folded
    gemm_tf32<1><<<ggrd, gblk>>>(K, W_K, b_K, gk);   // tf32-rounded
    gemm_tf32<1><<<ggrd, gblk>>>(V, W_V, b_V, gv);   // tf32-rounded

    dim3 agrd(SEQ / 128, N_HEADS, BATCH);  // (16, 16, 2)
    attn_tf32<<<agrd, 128, ATTN_SMEM_BYTES>>>(ga);

    gemm_tf32<0><<<ggrd, gblk>>>(ga, W_O, b_O, out); // plain fp32 out
}